// round 3
// baseline (speedup 1.0000x reference)
#include <cuda_runtime.h>
#include <cuda_bf16.h>
#include <cstddef>

// Problem constants (fixed by the reference)
#define NPTS 16384
#define CH   192
#define NH   16
#define NK   43
#define DEPTH 2
#define BN_EPS 1e-5f
#define PPB  8          // points per conv block

// ---------------- scratch (device globals; no allocation allowed) ----------
__device__ float g_tmp1[NPTS * CH];
__device__ float g_tmp2[NPTS * CH];
__device__ float g_tmp3[NPTS * CH];
__device__ float g_featbuf[NPTS * CH];
__device__ float g_stats[6 * 2 * CH];   // 6 stages x (sum[CH], sumsq[CH])
__device__ float g_st[6 * 2 * CH];      // 6 stages x (scale[CH], shift[CH])

// ---------------------------------------------------------------------------
__global__ void zero_stats_kernel(float* stats) {
    for (int i = threadIdx.x; i < 6 * 2 * CH; i += blockDim.x) stats[i] = 0.f;
}

// finalize BN: scale = g * rsqrt(var+eps), shift = b - mean*scale
__global__ void fin_kernel(const float* __restrict__ stats,
                           const float* __restrict__ g,
                           const float* __restrict__ b,
                           float* __restrict__ st) {
    int c = threadIdx.x;   // 192 threads
    float m = stats[c] * (1.0f / NPTS);
    float v = stats[CH + c] * (1.0f / NPTS) - m * m;
    float s = g[c] * rsqrtf(v + BN_EPS);
    st[c]      = s;
    st[CH + c] = b[c] - m * s;
}

// ---------------------------------------------------------------------------
// GEMM: out[N,192] = act(A)[N,192] @ W[192,192], with optional fused
// BN+ReLU on A load (fuse != 0 uses st_in = {scale[192], shift[192]}).
// Also accumulates per-output-channel sum / sumsq for the next BN.
// Block: 256 threads, 64 rows x 192 cols tile.
__global__ __launch_bounds__(256) void gemm192_kernel(
    const float* __restrict__ A, const float* __restrict__ W,
    float* __restrict__ out, const float* __restrict__ st_in, int fuse,
    float* __restrict__ gsum, float* __restrict__ gsq)
{
    __shared__ __align__(16) float sA[64][32];
    __shared__ __align__(16) float sB[32][192];

    const int tid = threadIdx.x;
    const int tx  = tid & 31;        // 0..31
    const int ty  = tid >> 5;        // 0..7
    const int row0 = blockIdx.x * 64;

    float acc[8][6];
#pragma unroll
    for (int r = 0; r < 8; r++)
#pragma unroll
        for (int q = 0; q < 6; q++) acc[r][q] = 0.f;

    for (int k0 = 0; k0 < 192; k0 += 32) {
        // --- load A tile (64x32) as float4, optional BN+ReLU transform ---
#pragma unroll
        for (int it = tid; it < 512; it += 256) {
            int r  = it >> 3;
            int kq = it & 7;
            float4 v = *(const float4*)(A + (size_t)(row0 + r) * CH + k0 + kq * 4);
            if (fuse) {
                float4 s = *(const float4*)(st_in + k0 + kq * 4);
                float4 t = *(const float4*)(st_in + CH + k0 + kq * 4);
                v.x = fmaxf(fmaf(v.x, s.x, t.x), 0.f);
                v.y = fmaxf(fmaf(v.y, s.y, t.y), 0.f);
                v.z = fmaxf(fmaf(v.z, s.z, t.z), 0.f);
                v.w = fmaxf(fmaf(v.w, s.w, t.w), 0.f);
            }
            *(float4*)&sA[r][kq * 4] = v;
        }
        // --- load B tile (32x192) ---
#pragma unroll
        for (int it = tid; it < 1536; it += 256) {
            int kk = it / 48;
            int cq = it - kk * 48;
            *(float4*)&sB[kk][cq * 4] =
                *(const float4*)(W + (size_t)(k0 + kk) * CH + cq * 4);
        }
        __syncthreads();

#pragma unroll
        for (int kk4 = 0; kk4 < 8; kk4++) {
            float4 av[8];
#pragma unroll
            for (int r = 0; r < 8; r++)
                av[r] = *(const float4*)&sA[ty * 8 + r][kk4 * 4];
#pragma unroll
            for (int j = 0; j < 4; j++) {
                float bv[6];
#pragma unroll
                for (int q = 0; q < 6; q++)
                    bv[q] = sB[kk4 * 4 + j][tx + 32 * q];
#pragma unroll
                for (int r = 0; r < 8; r++) {
                    float a = (j == 0) ? av[r].x : (j == 1) ? av[r].y
                            : (j == 2) ? av[r].z : av[r].w;
#pragma unroll
                    for (int q = 0; q < 6; q++)
                        acc[r][q] = fmaf(a, bv[q], acc[r][q]);
                }
            }
        }
        __syncthreads();
    }

    // --- write out + per-channel stats ---
    float cs[6], c2[6];
#pragma unroll
    for (int q = 0; q < 6; q++) { cs[q] = 0.f; c2[q] = 0.f; }
#pragma unroll
    for (int r = 0; r < 8; r++) {
        float* orow = out + (size_t)(row0 + ty * 8 + r) * CH;
#pragma unroll
        for (int q = 0; q < 6; q++) {
            float v = acc[r][q];
            orow[tx + 32 * q] = v;
            cs[q] += v;
            c2[q] = fmaf(v, v, c2[q]);
        }
    }
#pragma unroll
    for (int q = 0; q < 6; q++) {
        atomicAdd(&gsum[tx + 32 * q], cs[q]);
        atomicAdd(&gsq [tx + 32 * q], c2[q]);
    }
}

// ---------------------------------------------------------------------------
// Depthwise kernel-point conv. One block = 192 threads (one per channel),
// PPB points per block. Computes influence in shared memory on the fly,
// applies BN1+ReLU to gathered fc1 outputs, aggregates, accumulates stats.
__global__ __launch_bounds__(192) void conv_kernel(
    const float* __restrict__ coord, const int* __restrict__ ref_idx,
    const float* __restrict__ kp, const float* __restrict__ tmp1,
    const float* __restrict__ st1, const float* __restrict__ Wk,
    float* __restrict__ out,
    float* __restrict__ gsum, float* __restrict__ gsq)
{
    __shared__ __align__(16) float s_wk[NK * CH];          // 33 KB
    __shared__ __align__(16) float s_inflT[NK][NH];        // [k][h]
    __shared__ int   s_ref[NH];
    __shared__ float s_nb[NH][3];
    __shared__ float s_kp[NK * 3];

    const int tid = threadIdx.x;   // channel index
    for (int i = tid; i < NK * CH; i += 192) s_wk[i] = Wk[i];
    for (int i = tid; i < NK * 3;  i += 192) s_kp[i] = kp[i];

    const float s1c = st1[tid];
    const float t1c = st1[CH + tid];
    float lsum = 0.f, lsq = 0.f;

    for (int p = 0; p < PPB; p++) {
        const int n = blockIdx.x * PPB + p;
        __syncthreads();   // prev iteration done reading s_ref / s_inflT; s_wk ready
        if (tid < NH) {
            int r = ref_idx[n * NH + tid];
            s_ref[tid] = r;
            s_nb[tid][0] = coord[r * 3 + 0] - coord[n * 3 + 0];
            s_nb[tid][1] = coord[r * 3 + 1] - coord[n * 3 + 1];
            s_nb[tid][2] = coord[r * 3 + 2] - coord[n * 3 + 2];
        }
        __syncthreads();
        for (int i = tid; i < NH * NK; i += 192) {
            int h = i / NK;
            int k = i - h * NK;
            float dx = s_nb[h][0] - s_kp[k * 3 + 0];
            float dy = s_nb[h][1] - s_kp[k * 3 + 1];
            float dz = s_nb[h][2] - s_kp[k * 3 + 2];
            float d  = sqrtf(fmaf(dx, dx, fmaf(dy, dy, dz * dz)));
            s_inflT[k][h] = fmaxf(1.0f - d, 0.0f);   // SIGMA == 1
        }
        __syncthreads();

        // a[h] = sum_k infl[h,k] * Wk[k,c]
        float acc[NH];
#pragma unroll
        for (int h = 0; h < NH; h++) acc[h] = 0.f;
        for (int k = 0; k < NK; k++) {
            float w = s_wk[k * CH + tid];
            const float4* ip = (const float4*)&s_inflT[k][0];
            float4 i0 = ip[0], i1 = ip[1], i2 = ip[2], i3 = ip[3];
            acc[0]  = fmaf(i0.x, w, acc[0]);  acc[1]  = fmaf(i0.y, w, acc[1]);
            acc[2]  = fmaf(i0.z, w, acc[2]);  acc[3]  = fmaf(i0.w, w, acc[3]);
            acc[4]  = fmaf(i1.x, w, acc[4]);  acc[5]  = fmaf(i1.y, w, acc[5]);
            acc[6]  = fmaf(i1.z, w, acc[6]);  acc[7]  = fmaf(i1.w, w, acc[7]);
            acc[8]  = fmaf(i2.x, w, acc[8]);  acc[9]  = fmaf(i2.y, w, acc[9]);
            acc[10] = fmaf(i2.z, w, acc[10]); acc[11] = fmaf(i2.w, w, acc[11]);
            acc[12] = fmaf(i3.x, w, acc[12]); acc[13] = fmaf(i3.y, w, acc[13]);
            acc[14] = fmaf(i3.z, w, acc[14]); acc[15] = fmaf(i3.w, w, acc[15]);
        }

        // gather fc1 rows (BN1+ReLU fused) and aggregate
        float o = 0.f;
#pragma unroll
        for (int h = 0; h < NH; h++) {
            float x = __ldg(tmp1 + (size_t)s_ref[h] * CH + tid);
            x = fmaxf(fmaf(x, s1c, t1c), 0.f);
            o = fmaf(acc[h], x, o);
        }
        out[(size_t)n * CH + tid] = o;
        lsum += o;
        lsq  = fmaf(o, o, lsq);
    }
    atomicAdd(&gsum[tid], lsum);
    atomicAdd(&gsq [tid], lsq);
}

// ---------------------------------------------------------------------------
// feat_out = relu(identity + BN3(tmp3))   (vectorized float4)
__global__ __launch_bounds__(256) void apply3_kernel(
    const float4* __restrict__ idf, const float4* __restrict__ t3,
    const float* __restrict__ st, float4* __restrict__ outf)
{
    int i  = blockIdx.x * blockDim.x + threadIdx.x;   // < NPTS*CH/4
    int cq = i % (CH / 4);
    float4 s = *(const float4*)(st + cq * 4);
    float4 t = *(const float4*)(st + CH + cq * 4);
    float4 x = t3[i];
    float4 d = idf[i];
    float4 r;
    r.x = fmaxf(d.x + fmaf(x.x, s.x, t.x), 0.f);
    r.y = fmaxf(d.y + fmaf(x.y, s.y, t.y), 0.f);
    r.z = fmaxf(d.z + fmaf(x.z, s.z, t.z), 0.f);
    r.w = fmaxf(d.w + fmaf(x.w, s.w, t.w), 0.f);
    outf[i] = r;
}

// ---------------------------------------------------------------------------
extern "C" void kernel_launch(void* const* d_in, const int* in_sizes, int n_in,
                              void* d_out, int out_size)
{
    const float* coord   = (const float*)d_in[0];
    const float* feat    = (const float*)d_in[1];
    const int*   ref_idx = (const int*)  d_in[2];
    const float* kp      = (const float*)d_in[3];
    const float* W1      = (const float*)d_in[4];
    const float* Wk      = (const float*)d_in[5];
    const float* W3      = (const float*)d_in[6];
    const float* g1      = (const float*)d_in[7];
    const float* b1      = (const float*)d_in[8];
    const float* g2      = (const float*)d_in[9];
    const float* b2      = (const float*)d_in[10];
    const float* g3      = (const float*)d_in[11];
    const float* b3      = (const float*)d_in[12];
    float* out = (float*)d_out;

    float *tmp1, *tmp2, *tmp3, *featbuf, *stats, *st;
    cudaGetSymbolAddress((void**)&tmp1,    g_tmp1);
    cudaGetSymbolAddress((void**)&tmp2,    g_tmp2);
    cudaGetSymbolAddress((void**)&tmp3,    g_tmp3);
    cudaGetSymbolAddress((void**)&featbuf, g_featbuf);
    cudaGetSymbolAddress((void**)&stats,   g_stats);
    cudaGetSymbolAddress((void**)&st,      g_st);

    zero_stats_kernel<<<1, 256>>>(stats);

    const int NVEC = NPTS * CH / 4;             // 786432
    for (int i = 0; i < DEPTH; i++) {
        const float* fin_ = (i == 0) ? feat : featbuf;
        float* fout = (i == DEPTH - 1) ? out : featbuf;
        const int s0 = 3 * i + 0, s1 = 3 * i + 1, s2 = 3 * i + 2;

        // fc1 (+BN1 stats)
        gemm192_kernel<<<NPTS / 64, 256>>>(
            fin_, W1 + (size_t)i * CH * CH, tmp1, nullptr, 0,
            stats + s0 * 2 * CH, stats + s0 * 2 * CH + CH);
        fin_kernel<<<1, CH>>>(stats + s0 * 2 * CH, g1 + i * CH, b1 + i * CH,
                              st + s0 * 2 * CH);

        // KP depthwise conv (BN1+ReLU fused at gather; BN2 stats out)
        conv_kernel<<<NPTS / PPB, CH>>>(
            coord, ref_idx, kp, tmp1, st + s0 * 2 * CH,
            Wk + (size_t)i * NK * CH, tmp2,
            stats + s1 * 2 * CH, stats + s1 * 2 * CH + CH);
        fin_kernel<<<1, CH>>>(stats + s1 * 2 * CH, g2 + i * CH, b2 + i * CH,
                              st + s1 * 2 * CH);

        // fc3 (BN2+ReLU fused on A load; BN3 stats out)
        gemm192_kernel<<<NPTS / 64, 256>>>(
            tmp2, W3 + (size_t)i * CH * CH, tmp3, st + s1 * 2 * CH, 1,
            stats + s2 * 2 * CH, stats + s2 * 2 * CH + CH);
        fin_kernel<<<1, CH>>>(stats + s2 * 2 * CH, g3 + i * CH, b3 + i * CH,
                              st + s2 * 2 * CH);

        // skip + BN3 + ReLU
        apply3_kernel<<<NVEC / 256, 256>>>(
            (const float4*)fin_, (const float4*)tmp3, st + s2 * 2 * CH,
            (float4*)fout);
    }
}